// round 15
// baseline (speedup 1.0000x reference)
#include <cuda_runtime.h>
#include <cuda_fp16.h>
#include <cstdint>

#define NN 50000
#define DD 128
#define EE 600000
#define PP 100000
#define STR 136

// ---------------- mma.sync helpers (sm_80-base ISA) --------------------------
__device__ __forceinline__ uint32_t smem_to_u32(const void* p) {
    uint32_t a;
    asm("{ .reg .u64 t; cvta.to.shared.u64 t, %1; cvt.u32.u64 %0, t; }"
        : "=r"(a) : "l"(p));
    return a;
}

#define LDSM_X4(r0, r1, r2, r3, addr) \
    asm volatile("ldmatrix.sync.aligned.m8n8.x4.shared.b16 {%0,%1,%2,%3}, [%4];" \
        : "=r"(r0), "=r"(r1), "=r"(r2), "=r"(r3) : "r"(addr))

#define MMA_F16(d, a, b) \
    asm("mma.sync.aligned.m16n8k16.row.col.f32.f16.f16.f32 " \
        "{%0,%1,%2,%3}, {%4,%5,%6,%7}, {%8,%9}, {%0,%1,%2,%3};" \
        : "+f"((d)[0]), "+f"((d)[1]), "+f"((d)[2]), "+f"((d)[3]) \
        : "r"((a)[0]), "r"((a)[1]), "r"((a)[2]), "r"((a)[3]), \
          "r"((b)[0]), "r"((b)[1]))

// split fp32 pair into fp16 hi pair + fp16 residual pair (packed)
__device__ __forceinline__ void split2h(float a, float b, uint32_t& hi, uint32_t& lo) {
    __half ha = __float2half_rn(a), hb = __float2half_rn(b);
    float ra = a - __half2float(ha), rb = b - __half2float(hb);
    __half2 H(ha, hb);
    __half2 L(__float2half_rn(ra), __float2half_rn(rb));
    hi = *reinterpret_cast<uint32_t*>(&H);
    lo = *reinterpret_cast<uint32_t*>(&L);
}

// --------- single-buffered fragment GEMM (fp16 2-term) ----------
struct Frag {
    uint32_t ah[2][4], al[2][4];
    uint32_t bh[8][2];
};

__device__ __forceinline__ void load_frag(
    Frag& f, uint32_t sAhi, uint32_t sAlo, uint32_t sBhi,
    int k0, int rA, int rB, int cOff)
{
#pragma unroll
    for (int mf = 0; mf < 2; mf++) {
        uint32_t ad = sAhi + ((rA + mf * 16) * STR + k0 + cOff) * 2;
        LDSM_X4(f.ah[mf][0], f.ah[mf][1], f.ah[mf][2], f.ah[mf][3], ad);
        uint32_t ad2 = sAlo + ((rA + mf * 16) * STR + k0 + cOff) * 2;
        LDSM_X4(f.al[mf][0], f.al[mf][1], f.al[mf][2], f.al[mf][3], ad2);
    }
#pragma unroll
    for (int q = 0; q < 4; q++) {
        uint32_t t0, t1, t2, t3;
        uint32_t bd = sBhi + ((rB + q * 16) * STR + k0 + cOff) * 2;
        LDSM_X4(t0, t1, t2, t3, bd);
        f.bh[2 * q][0] = t0; f.bh[2 * q + 1][0] = t1;
        f.bh[2 * q][1] = t2; f.bh[2 * q + 1][1] = t3;
    }
}

// term-major: consecutive MMAs hit different accumulators
__device__ __forceinline__ void mma_frag(float acc[2][8][4], const Frag& f) {
#pragma unroll
    for (int mf = 0; mf < 2; mf++)
#pragma unroll
        for (int nf = 0; nf < 8; nf++)
            MMA_F16(acc[mf][nf], f.ah[mf], f.bh[nf]);
#pragma unroll
    for (int mf = 0; mf < 2; mf++)
#pragma unroll
        for (int nf = 0; nf < 8; nf++)
            MMA_F16(acc[mf][nf], f.al[mf], f.bh[nf]);
}

__device__ __forceinline__ void gemm_single(
    float acc[2][8][4], uint32_t sAhi, uint32_t sAlo, uint32_t sBhi,
    int rA, int rB, int cOff)
{
    Frag f;
#pragma unroll
    for (int ks = 0; ks < 8; ks++) {
        load_frag(f, sAhi, sAlo, sBhi, ks * 16, rA, rB, cOff);
        mma_frag(acc, f);
    }
}

// ---- scratch ----
__device__ float g_hA[NN * DD];
__device__ float g_hB[NN * DD];
__device__ float g_agg[NN * DD];
__device__ float g_invdeg[NN];
__device__ int   g_deg[NN];
__device__ int   g_incl[NN];
__device__ int   g_bsum[64];
__device__ int   g_rows[NN + 1];
__device__ int   g_cursor[NN];
__device__ int   g_csr[EE];
__device__ __align__(16) __half g_w1h[DD * DD];
__device__ __align__(16) __half g_w2h[DD * DD];
__device__ __align__(16) __half g_swh[6 * DD * DD];

#define T_ELEMS (128 * STR)
#define TILE_SMEM_BYTES (3 * T_ELEMS * 2)   // 104448; 2 blocks/SM fit

// ---------------------------------------------------------------
// CSR build
// ---------------------------------------------------------------
__global__ void deg_count_kernel(const int* __restrict__ dst) {
    int i = blockIdx.x * blockDim.x + threadIdx.x;
    if (i < EE) atomicAdd(&g_deg[dst[i]], 1);
}

__global__ void scan1_kernel() {
    __shared__ int sh[1024];
    int b = blockIdx.x, t = threadIdx.x;
    int i = b * 1024 + t;
    int v = (i < NN) ? g_deg[i] : 0;
    sh[t] = v;
    __syncthreads();
#pragma unroll
    for (int off = 1; off < 1024; off <<= 1) {
        int x = (t >= off) ? sh[t - off] : 0;
        __syncthreads();
        sh[t] += x;
        __syncthreads();
    }
    if (i < NN) g_incl[i] = sh[t];
    if (t == 1023) g_bsum[b] = sh[1023];
}

__global__ void scan3_kernel() {
    int i = blockIdx.x * blockDim.x + threadIdx.x;
    if (i < NN) {
        int blk = i >> 10;
        int base = 0;
        for (int b = 0; b < blk; b++) base += g_bsum[b];
        int dg = g_deg[i];
        int excl = g_incl[i] - dg + base;
        g_rows[i] = excl;
        g_cursor[i] = excl;
        g_invdeg[i] = 1.0f / (float)max(dg, 1);
        g_deg[i] = 0;
    }
    if (i == 0) g_rows[NN] = EE;
}

__global__ void fill_kernel(const int* __restrict__ src, const int* __restrict__ dst) {
    int e = blockIdx.x * blockDim.x + threadIdx.x;
    if (e < EE) {
        int p = atomicAdd(&g_cursor[dst[e]], 1);
        g_csr[p] = src[e];
    }
}

// ---------------------------------------------------------------
// weight prep: transpose + truncate to fp16
// ---------------------------------------------------------------
__global__ void prep_w_kernel(const float* __restrict__ W_self,
                              const float* __restrict__ W_neigh,
                              const float* __restrict__ Wp1,
                              const float* __restrict__ Wp2) {
    int idx = blockIdx.x * blockDim.x + threadIdx.x;
    if (idx >= 3 * DD * DD) return;
    int l = idx >> 14;
    int r = idx & (DD * DD - 1);
    int n = r >> 7, k = r & 127;
    g_swh[(l * 2 + 0) * DD * DD + n * DD + k] =
        __float2half_rn(W_self[l * DD * DD + k * DD + n]);
    g_swh[(l * 2 + 1) * DD * DD + n * DD + k] =
        __float2half_rn(W_neigh[l * DD * DD + k * DD + n]);
    if (l == 0) {
        g_w1h[n * DD + k] = __float2half_rn(Wp1[k * DD + n]);
        g_w2h[n * DD + k] = __float2half_rn(Wp2[k * DD + n]);
    }
}

// ---------------------------------------------------------------
// aggregate: one warp per node
// ---------------------------------------------------------------
__global__ void aggregate_kernel(const float* __restrict__ h, float* __restrict__ agg) {
    int w = (blockIdx.x * blockDim.x + threadIdx.x) >> 5;
    int lane = threadIdx.x & 31;
    if (w >= NN) return;
    int rs = g_rows[w], re = g_rows[w + 1];
    float4 acc = {0.f, 0.f, 0.f, 0.f};
    int i = rs;
    for (; i + 3 < re; i += 4) {
        int s0 = __ldg(&g_csr[i]);
        int s1 = __ldg(&g_csr[i + 1]);
        int s2 = __ldg(&g_csr[i + 2]);
        int s3 = __ldg(&g_csr[i + 3]);
        float4 a = __ldg((const float4*)(h + (size_t)s0 * DD) + lane);
        float4 b = __ldg((const float4*)(h + (size_t)s1 * DD) + lane);
        float4 c = __ldg((const float4*)(h + (size_t)s2 * DD) + lane);
        float4 d = __ldg((const float4*)(h + (size_t)s3 * DD) + lane);
        acc.x += a.x + b.x + c.x + d.x;
        acc.y += a.y + b.y + c.y + d.y;
        acc.z += a.z + b.z + c.z + d.z;
        acc.w += a.w + b.w + c.w + d.w;
    }
    for (; i < re; i++) {
        int s0 = __ldg(&g_csr[i]);
        float4 a = __ldg((const float4*)(h + (size_t)s0 * DD) + lane);
        acc.x += a.x; acc.y += a.y; acc.z += a.z; acc.w += a.w;
    }
    float sc = g_invdeg[w];
    acc.x *= sc; acc.y *= sc; acc.z *= sc; acc.w *= sc;
    ((float4*)(agg + (size_t)w * DD))[lane] = acc;
}

// ---------------------------------------------------------------
// sage layer via mma.sync (fp16 2-term, 2 blocks/SM)
// ---------------------------------------------------------------
__global__ void __launch_bounds__(256, 2) sage_mma_kernel(
    const float* __restrict__ A,
    const float* __restrict__ G,
    const float* __restrict__ bias,
    float* __restrict__ out,
    int do_relu, int layer)
{
    extern __shared__ __half hsm[];
    __half* Ahi = hsm;
    __half* Alo = hsm + T_ELEMS;
    __half* Bhi = hsm + 2 * T_ELEMS;
    __shared__ float s_bias[DD];

    int tid = threadIdx.x;
    int lane = tid & 31;
    int wid = tid >> 5;
    int wm = wid >> 1, wn = wid & 1;
    int m0 = wm * 32, n0 = wn * 64;
    int row0 = blockIdx.x * 128;

    if (tid < DD) s_bias[tid] = bias[tid];

    uint32_t sAhi = smem_to_u32(Ahi), sAlo = smem_to_u32(Alo);
    uint32_t sBhi = smem_to_u32(Bhi);
    int rA = m0 + (lane & 15);
    int rB = n0 + (lane & 15);
    int cOff = (lane >> 4) * 8;
    int gq = lane >> 2, tq = lane & 3;

    float acc[2][8][4];
#pragma unroll
    for (int mf = 0; mf < 2; mf++)
#pragma unroll
        for (int nf = 0; nf < 8; nf++)
#pragma unroll
            for (int j = 0; j < 4; j++) acc[mf][nf][j] = 0.f;

    int p = tid >> 1;
    int half = tid & 1;
    int rc = min(row0 + p, NN - 1);

    for (int phase = 0; phase < 2; phase++) {
        const float* Ap = phase ? G : A;
        const __half* Wh = g_swh + (size_t)(layer * 2 + phase) * DD * DD;

        const float4* hs = (const float4*)(Ap + (size_t)rc * DD + half * 64);
#pragma unroll
        for (int i = 0; i < 16; i++) {
            float4 v = hs[i];
            uint32_t h01, l01, h23, l23;
            split2h(v.x, v.y, h01, l01);
            split2h(v.z, v.w, h23, l23);
            int k = half * 64 + i * 4;
            uint2 vh = {h01, h23};
            uint2 vl = {l01, l23};
            *(uint2*)&Ahi[p * STR + k] = vh;
            *(uint2*)&Alo[p * STR + k] = vl;
        }
        {
            const uint2* wh = (const uint2*)Wh + p * 32 + half * 16;
#pragma unroll
            for (int i = 0; i < 16; i++) {
                int k = half * 64 + i * 4;
                *(uint2*)&Bhi[p * STR + k] = wh[i];
            }
        }
        __syncthreads();

        gemm_single(acc, sAhi, sAlo, sBhi, rA, rB, cOff);
        __syncthreads();
    }

    // epilogue
#pragma unroll
    for (int mf = 0; mf < 2; mf++) {
        int r1 = row0 + m0 + mf * 16 + gq;
        int r2 = r1 + 8;
#pragma unroll
        for (int nf = 0; nf < 8; nf++) {
            int c = n0 + nf * 8 + 2 * tq;
            float v0 = acc[mf][nf][0] + s_bias[c];
            float v1 = acc[mf][nf][1] + s_bias[c + 1];
            float v2 = acc[mf][nf][2] + s_bias[c];
            float v3 = acc[mf][nf][3] + s_bias[c + 1];
            if (do_relu) {
                v0 = fmaxf(v0, 0.f); v1 = fmaxf(v1, 0.f);
                v2 = fmaxf(v2, 0.f); v3 = fmaxf(v3, 0.f);
            }
            if (r1 < NN) { float2 o = {v0, v1}; *(float2*)(out + (size_t)r1 * DD + c) = o; }
            if (r2 < NN) { float2 o = {v2, v3}; *(float2*)(out + (size_t)r2 * DD + c) = o; }
        }
    }
}

// ---------------------------------------------------------------
// predictor via mma.sync (fp16 2-term, 2 blocks/SM)
// ---------------------------------------------------------------
__global__ void __launch_bounds__(256, 2) predictor_mma_kernel(
    const float* __restrict__ h,
    const int* __restrict__ pos_src, const int* __restrict__ pos_dst,
    const int* __restrict__ neg_src, const int* __restrict__ neg_dst,
    const float* __restrict__ bp1, const float* __restrict__ bp2,
    const float* __restrict__ Wp3, const float* __restrict__ bp3,
    float* __restrict__ out)
{
    extern __shared__ __half hsm[];
    __half* Ahi = hsm;
    __half* Alo = hsm + T_ELEMS;
    __half* Bhi = hsm + 2 * T_ELEMS;
    __shared__ float s_b1[DD], s_b2[DD], s_w3[DD];
    __shared__ float s_part[DD][2];

    int tid = threadIdx.x;
    int lane = tid & 31;
    int wid = tid >> 5;
    int wm = wid >> 1, wn = wid & 1;
    int m0 = wm * 32, n0 = wn * 64;
    int g0 = blockIdx.x * 128;

    if (tid < DD) {
        s_b1[tid] = bp1[tid];
        s_b2[tid] = bp2[tid];
        s_w3[tid] = Wp3[tid];
    }

    int p = tid >> 1;
    int half = tid & 1;

    // ---- stage 1: A = split(h[s]*h[d]), B = fp16(W1^T) ----
    {
        int g = g0 + p;
        int gm = g < 2 * PP ? g : 2 * PP - 1;
        int s, d;
        if (gm < PP) { s = pos_src[gm]; d = pos_dst[gm]; }
        else         { s = neg_src[gm - PP]; d = neg_dst[gm - PP]; }
        const float4* hs = (const float4*)(h + (size_t)s * DD + half * 64);
        const float4* hd = (const float4*)(h + (size_t)d * DD + half * 64);
#pragma unroll
        for (int i = 0; i < 16; i++) {
            float4 a = hs[i];
            float4 bv = hd[i];
            float e0 = a.x * bv.x, e1 = a.y * bv.y, e2 = a.z * bv.z, e3 = a.w * bv.w;
            uint32_t h01, l01, h23, l23;
            split2h(e0, e1, h01, l01);
            split2h(e2, e3, h23, l23);
            int k = half * 64 + i * 4;
            uint2 vh = {h01, h23};
            uint2 vl = {l01, l23};
            *(uint2*)&Ahi[p * STR + k] = vh;
            *(uint2*)&Alo[p * STR + k] = vl;
        }
        const uint2* w1h = (const uint2*)g_w1h + p * 32 + half * 16;
#pragma unroll
        for (int i = 0; i < 16; i++) {
            int k = half * 64 + i * 4;
            *(uint2*)&Bhi[p * STR + k] = w1h[i];
        }
    }
    __syncthreads();

    uint32_t sAhi = smem_to_u32(Ahi), sAlo = smem_to_u32(Alo);
    uint32_t sBhi = smem_to_u32(Bhi);
    int rA = m0 + (lane & 15);
    int rB = n0 + (lane & 15);
    int cOff = (lane >> 4) * 8;
    int gq = lane >> 2, tq = lane & 3;

    float acc[2][8][4];

    // ================= GEMM 1 =================
#pragma unroll
    for (int mf = 0; mf < 2; mf++)
#pragma unroll
        for (int nf = 0; nf < 8; nf++)
#pragma unroll
            for (int j = 0; j < 4; j++) acc[mf][nf][j] = 0.f;

    gemm_single(acc, sAhi, sAlo, sBhi, rA, rB, cOff);
    __syncthreads();

    // ---- epilogue1: t1 = relu(D + bp1) -> A tiles; reload B with W2 ----
#pragma unroll
    for (int mf = 0; mf < 2; mf++) {
        int r1 = m0 + mf * 16 + gq;
        int r2 = r1 + 8;
#pragma unroll
        for (int nf = 0; nf < 8; nf++) {
            int c = n0 + nf * 8 + 2 * tq;
            float v0 = fmaxf(acc[mf][nf][0] + s_b1[c], 0.f);
            float v1 = fmaxf(acc[mf][nf][1] + s_b1[c + 1], 0.f);
            float v2 = fmaxf(acc[mf][nf][2] + s_b1[c], 0.f);
            float v3 = fmaxf(acc[mf][nf][3] + s_b1[c + 1], 0.f);
            uint32_t hh, ll;
            split2h(v0, v1, hh, ll);
            *(uint32_t*)&Ahi[r1 * STR + c] = hh;
            *(uint32_t*)&Alo[r1 * STR + c] = ll;
            split2h(v2, v3, hh, ll);
            *(uint32_t*)&Ahi[r2 * STR + c] = hh;
            *(uint32_t*)&Alo[r2 * STR + c] = ll;
        }
    }
    {
        const uint2* w2h = (const uint2*)g_w2h + p * 32 + half * 16;
#pragma unroll
        for (int i = 0; i < 16; i++) {
            int k = half * 64 + i * 4;
            *(uint2*)&Bhi[p * STR + k] = w2h[i];
        }
    }
    __syncthreads();

    // ================= GEMM 2 =================
#pragma unroll
    for (int mf = 0; mf < 2; mf++)
#pragma unroll
        for (int nf = 0; nf < 8; nf++)
#pragma unroll
            for (int j = 0; j < 4; j++) acc[mf][nf][j] = 0.f;

    gemm_single(acc, sAhi, sAlo, sBhi, rA, rB, cOff);

    // ---- epilogue2: score = relu(D + bp2) . w3 (+bp3) ----
#pragma unroll
    for (int mf = 0; mf < 2; mf++) {
        float p0 = 0.f, p1 = 0.f;
#pragma unroll
        for (int nf = 0; nf < 8; nf++) {
            int c = n0 + nf * 8 + 2 * tq;
            p0 += fmaxf(acc[mf][nf][0] + s_b2[c], 0.f) * s_w3[c]
                + fmaxf(acc[mf][nf][1] + s_b2[c + 1], 0.f) * s_w3[c + 1];
            p1 += fmaxf(acc[mf][nf][2] + s_b2[c], 0.f) * s_w3[c]
                + fmaxf(acc[mf][nf][3] + s_b2[c + 1], 0.f) * s_w3[c + 1];
        }
        p0 += __shfl_xor_sync(0xffffffffu, p0, 1);
        p0 += __shfl_xor_sync(0xffffffffu, p0, 2);
        p1 += __shfl_xor_sync(0xffffffffu, p1, 1);
        p1 += __shfl_xor_sync(0xffffffffu, p1, 2);
        if (tq == 0) {
            s_part[m0 + mf * 16 + gq][wn] = p0;
            s_part[m0 + mf * 16 + gq + 8][wn] = p1;
        }
    }
    __syncthreads();
    if (tid < 128) {
        int g = g0 + tid;
        if (g < 2 * PP) out[g] = s_part[tid][0] + s_part[tid][1] + bp3[0];
    }
}

// ---------------------------------------------------------------
// launch
// ---------------------------------------------------------------
extern "C" void kernel_launch(void* const* d_in, const int* in_sizes, int n_in,
                              void* d_out, int out_size) {
    const float* x       = (const float*)d_in[0];
    const float* W_self  = (const float*)d_in[1];
    const float* W_neigh = (const float*)d_in[2];
    const float* b       = (const float*)d_in[3];
    const float* Wp1     = (const float*)d_in[4];
    const float* bp1     = (const float*)d_in[5];
    const float* Wp2     = (const float*)d_in[6];
    const float* bp2     = (const float*)d_in[7];
    const float* Wp3     = (const float*)d_in[8];
    const float* bp3     = (const float*)d_in[9];
    const int* edge_src  = (const int*)d_in[10];
    const int* edge_dst  = (const int*)d_in[11];
    const int* pos_src   = (const int*)d_in[12];
    const int* pos_dst   = (const int*)d_in[13];
    const int* neg_src   = (const int*)d_in[14];
    const int* neg_dst   = (const int*)d_in[15];
    float* out = (float*)d_out;

    float *hA, *hB, *agg;
    cudaGetSymbolAddress((void**)&hA, g_hA);
    cudaGetSymbolAddress((void**)&hB, g_hB);
    cudaGetSymbolAddress((void**)&agg, g_agg);

    static int attr_done = 0;
    if (!attr_done) {
        cudaFuncSetAttribute(predictor_mma_kernel,
                             cudaFuncAttributeMaxDynamicSharedMemorySize, TILE_SMEM_BYTES);
        cudaFuncSetAttribute(sage_mma_kernel,
                             cudaFuncAttributeMaxDynamicSharedMemorySize, TILE_SMEM_BYTES);
        attr_done = 1;
    }

    const int NB = (NN + 1023) / 1024;

    deg_count_kernel<<<(EE + 255) / 256, 256>>>(edge_dst);
    prep_w_kernel<<<(3 * DD * DD + 255) / 256, 256>>>(W_self, W_neigh, Wp1, Wp2);
    scan1_kernel<<<NB, 1024>>>();
    scan3_kernel<<<(NN + 255) / 256, 256>>>();
    fill_kernel<<<(EE + 255) / 256, 256>>>(edge_src, edge_dst);

    // ---- layers ----
    const float* hin = x;
    float* outs[3] = {hA, hB, hA};
    for (int l = 0; l < 3; l++) {
        aggregate_kernel<<<(NN * 32 + 255) / 256, 256>>>(hin, agg);
        sage_mma_kernel<<<(NN + 127) / 128, 256, TILE_SMEM_BYTES>>>(
            hin, agg, b + (size_t)l * DD, outs[l], (l < 2) ? 1 : 0, l);
        hin = outs[l];
    }

    // ---- predictor ----
    predictor_mma_kernel<<<(2 * PP + 127) / 128, 256, TILE_SMEM_BYTES>>>(
        hin, pos_src, pos_dst, neg_src, neg_dst,
        bp1, bp2, Wp3, bp3, out);
}

// round 16
// speedup vs baseline: 1.0529x; 1.0529x over previous
#include <cuda_runtime.h>
#include <cuda_fp16.h>
#include <cstdint>

#define NN 50000
#define DD 128
#define EE 600000
#define PP 100000
#define STR 136

// ---------------- mma.sync helpers (sm_80-base ISA) --------------------------
__device__ __forceinline__ uint32_t smem_to_u32(const void* p) {
    uint32_t a;
    asm("{ .reg .u64 t; cvta.to.shared.u64 t, %1; cvt.u32.u64 %0, t; }"
        : "=r"(a) : "l"(p));
    return a;
}

#define LDSM_X4(r0, r1, r2, r3, addr) \
    asm volatile("ldmatrix.sync.aligned.m8n8.x4.shared.b16 {%0,%1,%2,%3}, [%4];" \
        : "=r"(r0), "=r"(r1), "=r"(r2), "=r"(r3) : "r"(addr))

#define MMA_F16(d, a, b) \
    asm("mma.sync.aligned.m16n8k16.row.col.f32.f16.f16.f32 " \
        "{%0,%1,%2,%3}, {%4,%5,%6,%7}, {%8,%9}, {%0,%1,%2,%3};" \
        : "+f"((d)[0]), "+f"((d)[1]), "+f"((d)[2]), "+f"((d)[3]) \
        : "r"((a)[0]), "r"((a)[1]), "r"((a)[2]), "r"((a)[3]), \
          "r"((b)[0]), "r"((b)[1]))

// split fp32 pair into fp16 hi pair + fp16 residual pair (packed)
__device__ __forceinline__ void split2h(float a, float b, uint32_t& hi, uint32_t& lo) {
    __half ha = __float2half_rn(a), hb = __float2half_rn(b);
    float ra = a - __half2float(ha), rb = b - __half2float(hb);
    __half2 H(ha, hb);
    __half2 L(__float2half_rn(ra), __float2half_rn(rb));
    hi = *reinterpret_cast<uint32_t*>(&H);
    lo = *reinterpret_cast<uint32_t*>(&L);
}

// --------- double-buffered fragment pipeline (fp16 2-term) ----------
struct Frag {
    uint32_t ah[2][4], al[2][4];
    uint32_t bh[8][2];
};

__device__ __forceinline__ void load_frag(
    Frag& f, uint32_t sAhi, uint32_t sAlo, uint32_t sBhi,
    int k0, int rA, int rB, int cOff)
{
#pragma unroll
    for (int mf = 0; mf < 2; mf++) {
        uint32_t ad = sAhi + ((rA + mf * 16) * STR + k0 + cOff) * 2;
        LDSM_X4(f.ah[mf][0], f.ah[mf][1], f.ah[mf][2], f.ah[mf][3], ad);
        uint32_t ad2 = sAlo + ((rA + mf * 16) * STR + k0 + cOff) * 2;
        LDSM_X4(f.al[mf][0], f.al[mf][1], f.al[mf][2], f.al[mf][3], ad2);
    }
#pragma unroll
    for (int q = 0; q < 4; q++) {
        uint32_t t0, t1, t2, t3;
        uint32_t bd = sBhi + ((rB + q * 16) * STR + k0 + cOff) * 2;
        LDSM_X4(t0, t1, t2, t3, bd);
        f.bh[2 * q][0] = t0; f.bh[2 * q + 1][0] = t1;
        f.bh[2 * q][1] = t2; f.bh[2 * q + 1][1] = t3;
    }
}

// term-major: consecutive MMAs hit different accumulators
__device__ __forceinline__ void mma_frag(float acc[2][8][4], const Frag& f) {
#pragma unroll
    for (int mf = 0; mf < 2; mf++)
#pragma unroll
        for (int nf = 0; nf < 8; nf++)
            MMA_F16(acc[mf][nf], f.ah[mf], f.bh[nf]);
#pragma unroll
    for (int mf = 0; mf < 2; mf++)
#pragma unroll
        for (int nf = 0; nf < 8; nf++)
            MMA_F16(acc[mf][nf], f.al[mf], f.bh[nf]);
}

__device__ __forceinline__ void gemm_pipelined(
    float acc[2][8][4], uint32_t sAhi, uint32_t sAlo, uint32_t sBhi,
    int rA, int rB, int cOff)
{
    Frag f0, f1;
    load_frag(f0, sAhi, sAlo, sBhi, 0, rA, rB, cOff);
#pragma unroll
    for (int ks = 0; ks < 8; ks++) {
        Frag& cur = (ks & 1) ? f1 : f0;
        Frag& nxt = (ks & 1) ? f0 : f1;
        if (ks < 7)
            load_frag(nxt, sAhi, sAlo, sBhi, (ks + 1) * 16, rA, rB, cOff);
        mma_frag(acc, cur);
    }
}

// ---- scratch ----
__device__ float g_hA[NN * DD];
__device__ float g_hB[NN * DD];
__device__ float g_agg[NN * DD];
__device__ float g_invdeg[NN];
__device__ int   g_deg[NN];
__device__ int   g_incl[NN];
__device__ int   g_bsum[64];
__device__ int   g_rows[NN + 1];
__device__ int   g_cursor[NN];
__device__ int   g_csr[EE];
__device__ __align__(16) __half g_w1h[DD * DD];
__device__ __align__(16) __half g_w2h[DD * DD];
__device__ __align__(16) __half g_swh[6 * DD * DD];

#define T_ELEMS (128 * STR)
#define TILE_SMEM_BYTES (4 * T_ELEMS * 2)   // Ahi, Alo, B0hi, B1hi = 139264

// ---------------------------------------------------------------
// CSR build
// ---------------------------------------------------------------
__global__ void deg_count_kernel(const int* __restrict__ dst) {
    int i = blockIdx.x * blockDim.x + threadIdx.x;
    if (i < EE) atomicAdd(&g_deg[dst[i]], 1);
}

__global__ void scan1_kernel() {
    __shared__ int sh[1024];
    int b = blockIdx.x, t = threadIdx.x;
    int i = b * 1024 + t;
    int v = (i < NN) ? g_deg[i] : 0;
    sh[t] = v;
    __syncthreads();
#pragma unroll
    for (int off = 1; off < 1024; off <<= 1) {
        int x = (t >= off) ? sh[t - off] : 0;
        __syncthreads();
        sh[t] += x;
        __syncthreads();
    }
    if (i < NN) g_incl[i] = sh[t];
    if (t == 1023) g_bsum[b] = sh[1023];
}

__global__ void scan3_kernel() {
    int i = blockIdx.x * blockDim.x + threadIdx.x;
    if (i < NN) {
        int blk = i >> 10;
        int base = 0;
        for (int b = 0; b < blk; b++) base += g_bsum[b];
        int dg = g_deg[i];
        int excl = g_incl[i] - dg + base;
        g_rows[i] = excl;
        g_cursor[i] = excl;
        g_invdeg[i] = 1.0f / (float)max(dg, 1);
        g_deg[i] = 0;
    }
    if (i == 0) g_rows[NN] = EE;
}

__global__ void fill_kernel(const int* __restrict__ src, const int* __restrict__ dst) {
    int e = blockIdx.x * blockDim.x + threadIdx.x;
    if (e < EE) {
        int p = atomicAdd(&g_cursor[dst[e]], 1);
        g_csr[p] = src[e];
    }
}

// ---------------------------------------------------------------
// weight prep: transpose + truncate to fp16
// ---------------------------------------------------------------
__global__ void prep_w_kernel(const float* __restrict__ W_self,
                              const float* __restrict__ W_neigh,
                              const float* __restrict__ Wp1,
                              const float* __restrict__ Wp2) {
    int idx = blockIdx.x * blockDim.x + threadIdx.x;
    if (idx >= 3 * DD * DD) return;
    int l = idx >> 14;
    int r = idx & (DD * DD - 1);
    int n = r >> 7, k = r & 127;
    g_swh[(l * 2 + 0) * DD * DD + n * DD + k] =
        __float2half_rn(W_self[l * DD * DD + k * DD + n]);
    g_swh[(l * 2 + 1) * DD * DD + n * DD + k] =
        __float2half_rn(W_neigh[l * DD * DD + k * DD + n]);
    if (l == 0) {
        g_w1h[n * DD + k] = __float2half_rn(Wp1[k * DD + n]);
        g_w2h[n * DD + k] = __float2half_rn(Wp2[k * DD + n]);
    }
}

// ---------------------------------------------------------------
// aggregate: one warp per node
// ---------------------------------------------------------------
__global__ void aggregate_kernel(const float* __restrict__ h, float* __restrict__ agg) {
    int w = (blockIdx.x * blockDim.x + threadIdx.x) >> 5;
    int lane = threadIdx.x & 31;
    if (w >= NN) return;
    int rs = g_rows[w], re = g_rows[w + 1];
    float4 acc = {0.f, 0.f, 0.f, 0.f};
    int i = rs;
    for (; i + 3 < re; i += 4) {
        int s0 = __ldg(&g_csr[i]);
        int s1 = __ldg(&g_csr[i + 1]);
        int s2 = __ldg(&g_csr[i + 2]);
        int s3 = __ldg(&g_csr[i + 3]);
        float4 a = __ldg((const float4*)(h + (size_t)s0 * DD) + lane);
        float4 b = __ldg((const float4*)(h + (size_t)s1 * DD) + lane);
        float4 c = __ldg((const float4*)(h + (size_t)s2 * DD) + lane);
        float4 d = __ldg((const float4*)(h + (size_t)s3 * DD) + lane);
        acc.x += a.x + b.x + c.x + d.x;
        acc.y += a.y + b.y + c.y + d.y;
        acc.z += a.z + b.z + c.z + d.z;
        acc.w += a.w + b.w + c.w + d.w;
    }
    for (; i < re; i++) {
        int s0 = __ldg(&g_csr[i]);
        float4 a = __ldg((const float4*)(h + (size_t)s0 * DD) + lane);
        acc.x += a.x; acc.y += a.y; acc.z += a.z; acc.w += a.w;
    }
    float sc = g_invdeg[w];
    acc.x *= sc; acc.y *= sc; acc.z *= sc; acc.w *= sc;
    ((float4*)(agg + (size_t)w * DD))[lane] = acc;
}

// ---------------------------------------------------------------
// sage layer via mma.sync (fp16 2-term, both weights staged upfront)
// ---------------------------------------------------------------
__global__ void __launch_bounds__(256, 1) sage_mma_kernel(
    const float* __restrict__ A,
    const float* __restrict__ G,
    const float* __restrict__ bias,
    float* __restrict__ out,
    int do_relu, int layer)
{
    extern __shared__ __half hsm[];
    __half* Ahi  = hsm;
    __half* Alo  = hsm + T_ELEMS;
    __half* B0hi = hsm + 2 * T_ELEMS;
    __half* B1hi = hsm + 3 * T_ELEMS;
    __shared__ float s_bias[DD];

    int tid = threadIdx.x;
    int lane = tid & 31;
    int wid = tid >> 5;
    int wm = wid >> 1, wn = wid & 1;
    int m0 = wm * 32, n0 = wn * 64;
    int row0 = blockIdx.x * 128;

    if (tid < DD) s_bias[tid] = bias[tid];

    uint32_t sAhi = smem_to_u32(Ahi), sAlo = smem_to_u32(Alo);
    uint32_t sB0hi = smem_to_u32(B0hi), sB1hi = smem_to_u32(B1hi);
    int rA = m0 + (lane & 15);
    int rB = n0 + (lane & 15);
    int cOff = (lane >> 4) * 8;
    int gq = lane >> 2, tq = lane & 3;

    float acc[2][8][4];
#pragma unroll
    for (int mf = 0; mf < 2; mf++)
#pragma unroll
        for (int nf = 0; nf < 8; nf++)
#pragma unroll
            for (int j = 0; j < 4; j++) acc[mf][nf][j] = 0.f;

    int p = tid >> 1;
    int half = tid & 1;
    int rc = min(row0 + p, NN - 1);

    // ---- stage: A = split(h rows); B0 = W0, B1 = W1 (both upfront) ----
    {
        const float4* hs = (const float4*)(A + (size_t)rc * DD + half * 64);
#pragma unroll
        for (int i = 0; i < 16; i++) {
            float4 v = hs[i];
            uint32_t h01, l01, h23, l23;
            split2h(v.x, v.y, h01, l01);
            split2h(v.z, v.w, h23, l23);
            int k = half * 64 + i * 4;
            uint2 vh = {h01, h23};
            uint2 vl = {l01, l23};
            *(uint2*)&Ahi[p * STR + k] = vh;
            *(uint2*)&Alo[p * STR + k] = vl;
        }
        const __half* W0 = g_swh + (size_t)(layer * 2 + 0) * DD * DD;
        const __half* W1 = g_swh + (size_t)(layer * 2 + 1) * DD * DD;
        const uint2* w0 = (const uint2*)W0 + p * 32 + half * 16;
        const uint2* w1 = (const uint2*)W1 + p * 32 + half * 16;
#pragma unroll
        for (int i = 0; i < 16; i++) {
            int k = half * 64 + i * 4;
            *(uint2*)&B0hi[p * STR + k] = w0[i];
            *(uint2*)&B1hi[p * STR + k] = w1[i];
        }
    }
    __syncthreads();

    // ---- GEMM phase 0: h @ Wself ----
    gemm_pipelined(acc, sAhi, sAlo, sB0hi, rA, rB, cOff);
    __syncthreads();

    // ---- restage A = split(agg) ----
    {
        const float4* hs = (const float4*)(G + (size_t)rc * DD + half * 64);
#pragma unroll
        for (int i = 0; i < 16; i++) {
            float4 v = hs[i];
            uint32_t h01, l01, h23, l23;
            split2h(v.x, v.y, h01, l01);
            split2h(v.z, v.w, h23, l23);
            int k = half * 64 + i * 4;
            uint2 vh = {h01, h23};
            uint2 vl = {l01, l23};
            *(uint2*)&Ahi[p * STR + k] = vh;
            *(uint2*)&Alo[p * STR + k] = vl;
        }
    }
    __syncthreads();

    // ---- GEMM phase 1: agg @ Wneigh (accumulate) ----
    gemm_pipelined(acc, sAhi, sAlo, sB1hi, rA, rB, cOff);

    // epilogue
#pragma unroll
    for (int mf = 0; mf < 2; mf++) {
        int r1 = row0 + m0 + mf * 16 + gq;
        int r2 = r1 + 8;
#pragma unroll
        for (int nf = 0; nf < 8; nf++) {
            int c = n0 + nf * 8 + 2 * tq;
            float v0 = acc[mf][nf][0] + s_bias[c];
            float v1 = acc[mf][nf][1] + s_bias[c + 1];
            float v2 = acc[mf][nf][2] + s_bias[c];
            float v3 = acc[mf][nf][3] + s_bias[c + 1];
            if (do_relu) {
                v0 = fmaxf(v0, 0.f); v1 = fmaxf(v1, 0.f);
                v2 = fmaxf(v2, 0.f); v3 = fmaxf(v3, 0.f);
            }
            if (r1 < NN) { float2 o = {v0, v1}; *(float2*)(out + (size_t)r1 * DD + c) = o; }
            if (r2 < NN) { float2 o = {v2, v3}; *(float2*)(out + (size_t)r2 * DD + c) = o; }
        }
    }
}

// ---------------------------------------------------------------
// predictor via mma.sync (fp16 2-term, W1+W2 staged upfront)
// ---------------------------------------------------------------
__global__ void __launch_bounds__(256, 1) predictor_mma_kernel(
    const float* __restrict__ h,
    const int* __restrict__ pos_src, const int* __restrict__ pos_dst,
    const int* __restrict__ neg_src, const int* __restrict__ neg_dst,
    const float* __restrict__ bp1, const float* __restrict__ bp2,
    const float* __restrict__ Wp3, const float* __restrict__ bp3,
    float* __restrict__ out)
{
    extern __shared__ __half hsm[];
    __half* Ahi  = hsm;
    __half* Alo  = hsm + T_ELEMS;
    __half* B0hi = hsm + 2 * T_ELEMS;
    __half* B1hi = hsm + 3 * T_ELEMS;
    __shared__ float s_b1[DD], s_b2[DD], s_w3[DD];
    __shared__ float s_part[DD][2];

    int tid = threadIdx.x;
    int lane = tid & 31;
    int wid = tid >> 5;
    int wm = wid >> 1, wn = wid & 1;
    int m0 = wm * 32, n0 = wn * 64;
    int g0 = blockIdx.x * 128;

    if (tid < DD) {
        s_b1[tid] = bp1[tid];
        s_b2[tid] = bp2[tid];
        s_w3[tid] = Wp3[tid];
    }

    int p = tid >> 1;
    int half = tid & 1;

    // ---- stage 1: A = split(h[s]*h[d]); B0 = W1, B1 = W2 (upfront) ----
    {
        int g = g0 + p;
        int gm = g < 2 * PP ? g : 2 * PP - 1;
        int s, d;
        if (gm < PP) { s = pos_src[gm]; d = pos_dst[gm]; }
        else         { s = neg_src[gm - PP]; d = neg_dst[gm - PP]; }
        const float4* hs = (const float4*)(h + (size_t)s * DD + half * 64);
        const float4* hd = (const float4*)(h + (size_t)d * DD + half * 64);
#pragma unroll
        for (int i = 0; i < 16; i++) {
            float4 a = hs[i];
            float4 bv = hd[i];
            float e0 = a.x * bv.x, e1 = a.y * bv.y, e2 = a.z * bv.z, e3 = a.w * bv.w;
            uint32_t h01, l01, h23, l23;
            split2h(e0, e1, h01, l01);
            split2h(e2, e3, h23, l23);
            int k = half * 64 + i * 4;
            uint2 vh = {h01, h23};
            uint2 vl = {l01, l23};
            *(uint2*)&Ahi[p * STR + k] = vh;
            *(uint2*)&Alo[p * STR + k] = vl;
        }
        const uint2* w1 = (const uint2*)g_w1h + p * 32 + half * 16;
        const uint2* w2 = (const uint2*)g_w2h + p * 32 + half * 16;
#pragma unroll
        for (int i = 0; i < 16; i++) {
            int k = half * 64 + i * 4;
            *(uint2*)&B0hi[p * STR + k] = w1[i];
            *(uint2*)&B1hi[p * STR + k] = w2[i];
        }
    }
    __syncthreads();

    uint32_t sAhi = smem_to_u32(Ahi), sAlo = smem_to_u32(Alo);
    uint32_t sB0hi = smem_to_u32(B0hi), sB1hi = smem_to_u32(B1hi);
    int rA = m0 + (lane & 15);
    int rB = n0 + (lane & 15);
    int cOff = (lane >> 4) * 8;
    int gq = lane >> 2, tq = lane & 3;

    float acc[2][8][4];

    // ================= GEMM 1 =================
#pragma unroll
    for (int mf = 0; mf < 2; mf++)
#pragma unroll
        for (int nf = 0; nf < 8; nf++)
#pragma unroll
            for (int j = 0; j < 4; j++) acc[mf][nf][j] = 0.f;

    gemm_pipelined(acc, sAhi, sAlo, sB0hi, rA, rB, cOff);
    __syncthreads();

    // ---- epilogue1: t1 = relu(D + bp1) -> A tiles ----
#pragma unroll
    for (int mf = 0; mf < 2; mf++) {
        int r1 = m0 + mf * 16 + gq;
        int r2 = r1 + 8;
#pragma unroll
        for (int nf = 0; nf < 8; nf++) {
            int c = n0 + nf * 8 + 2 * tq;
            float v0 = fmaxf(acc[mf][nf][0] + s_b1[c], 0.f);
            float v1 = fmaxf(acc[mf][nf][1] + s_b1[c + 1], 0.f);
            float v2 = fmaxf(acc[mf][nf][2] + s_b1[c], 0.f);
            float v3 = fmaxf(acc[mf][nf][3] + s_b1[c + 1], 0.f);
            uint32_t hh, ll;
            split2h(v0, v1, hh, ll);
            *(uint32_t*)&Ahi[r1 * STR + c] = hh;
            *(uint32_t*)&Alo[r1 * STR + c] = ll;
            split2h(v2, v3, hh, ll);
            *(uint32_t*)&Ahi[r2 * STR + c] = hh;
            *(uint32_t*)&Alo[r2 * STR + c] = ll;
        }
    }
    __syncthreads();

    // ================= GEMM 2 =================
#pragma unroll
    for (int mf = 0; mf < 2; mf++)
#pragma unroll
        for (int nf = 0; nf < 8; nf++)
#pragma unroll
            for (int j = 0; j < 4; j++) acc[mf][nf][j] = 0.f;

    gemm_pipelined(acc, sAhi, sAlo, sB1hi, rA, rB, cOff);

    // ---- epilogue2: score = relu(D + bp2) . w3 (+bp3) ----
#pragma unroll
    for (int mf = 0; mf < 2; mf++) {
        float p0 = 0.f, p1 = 0.f;
#pragma unroll
        for (int nf = 0; nf < 8; nf++) {
            int c = n0 + nf * 8 + 2 * tq;
            p0 += fmaxf(acc[mf][nf][0] + s_b2[c], 0.f) * s_w3[c]
                + fmaxf(acc[mf][nf][1] + s_b2[c + 1], 0.f) * s_w3[c + 1];
            p1 += fmaxf(acc[mf][nf][2] + s_b2[c], 0.f) * s_w3[c]
                + fmaxf(acc[mf][nf][3] + s_b2[c + 1], 0.f) * s_w3[c + 1];
        }
        p0 += __shfl_xor_sync(0xffffffffu, p0, 1);
        p0 += __shfl_xor_sync(0xffffffffu, p0, 2);
        p1 += __shfl_xor_sync(0xffffffffu, p1, 1);
        p1 += __shfl_xor_sync(0xffffffffu, p1, 2);
        if (tq == 0) {
            s_part[m0 + mf * 16 + gq][wn] = p0;
            s_part[m0 + mf * 16 + gq + 8][wn] = p1;
        }
    }
    __syncthreads();
    if (tid < 128) {
        int g = g0 + tid;
        if (g < 2 * PP) out[g] = s_part[tid][0] + s_part[tid][1] + bp3[0];
    }
}

// ---------------------------------------------------------------
// launch
// ---------------------------------------------------------------
extern "C" void kernel_launch(void* const* d_in, const int* in_sizes, int n_in,
                              void* d_out, int out_size) {
    const float* x       = (const float*)d_in[0];
    const float* W_self  = (const float*)d_in[1];
    const float* W_neigh = (const float*)d_in[2];
    const float* b       = (const float*)d_in[3];
    const float* Wp1     = (const float*)d_in[4];
    const float* bp1     = (const float*)d_in[5];
    const float* Wp2     = (const float*)d_in[6];
    const float* bp2     = (const float*)d_in[7];
    const float* Wp3     = (const float*)d_in[8];
    const float* bp3     = (const float*)d_in[9];
    const int* edge_src  = (const int*)d_in[10];
    const int* edge_dst  = (const int*)d_in[11];
    const int* pos_src   = (const int*)d_in[12];
    const int* pos_dst   = (const int*)d_in[13];
    const int* neg_src   = (const int*)d_in[14];
    const int* neg_dst   = (const int*)d_in[15];
    float* out = (float*)d_out;

    float *hA, *hB, *agg;
    cudaGetSymbolAddress((void**)&hA, g_hA);
    cudaGetSymbolAddress((void**)&hB, g_hB);
    cudaGetSymbolAddress((void**)&agg, g_agg);

    static int attr_done = 0;
    if (!attr_done) {
        cudaFuncSetAttribute(predictor_mma_kernel,
                             cudaFuncAttributeMaxDynamicSharedMemorySize, TILE_SMEM_BYTES);
        cudaFuncSetAttribute(sage_mma_kernel,
                             cudaFuncAttributeMaxDynamicSharedMemorySize, TILE_SMEM_BYTES);
        attr_done = 1;
    }

    const int NB = (NN + 1023) / 1024;

    deg_count_kernel<<<(EE + 255) / 256, 256>>>(edge_dst);
    prep_w_kernel<<<(3 * DD * DD + 255) / 256, 256>>>(W_self, W_neigh, Wp1, Wp2);
    scan1_kernel<<<NB, 1024>>>();
    scan3_kernel<<<(NN + 255) / 256, 256>>>();
    fill_kernel<<<(EE + 255) / 256, 256>>>(edge_src, edge_dst);

    // ---- layers ----
    const float* hin = x;
    float* outs[3] = {hA, hB, hA};
    for (int l = 0; l < 3; l++) {
        aggregate_kernel<<<(NN * 32 + 255) / 256, 256>>>(hin, agg);
        sage_mma_kernel<<<(NN + 127) / 128, 256, TILE_SMEM_BYTES>>>(
            hin, agg, b + (size_t)l * DD, outs[l], (l < 2) ? 1 : 0, l);
        hin = outs[l];
    }

    // ---- predictor ----
    predictor_mma_kernel<<<(2 * PP + 127) / 128, 256, TILE_SMEM_BYTES>>>(
        hin, pos_src, pos_dst, neg_src, neg_dst,
        bp1, bp2, Wp3, bp3, out);
}